// round 13
// baseline (speedup 1.0000x reference)
#include <cuda_runtime.h>
#include <cstdint>

// Fused QKV projection + RoPE + (B,H,S,D) transpose.
// tf32 mma.sync, 64x64 warp tiles, cp.async 3-stage pipeline.
// BM=256 BN=128 BK=32, 256 threads (warp grid 4m x 2n, warp tile 64x64).

namespace {
constexpr int NK = 128;                   // 4096/32 k-tiles
constexpr int ROWB = 144;                 // smem row pitch (128B data + 16B pad)
constexpr int A_TILE = 256 * ROWB;        // 36864
constexpr int B_TILE = 128 * ROWB;        // 18432
constexpr int STAGE = A_TILE + B_TILE;    // 55296
constexpr int STAGES = 3;
constexpr int SMEM_BYTES = STAGES * STAGE; // 165888
}

__device__ __forceinline__ uint32_t cvta_smem(const void* p) {
    uint32_t a;
    asm("{ .reg .u64 t; cvta.to.shared.u64 t, %1; cvt.u32.u64 %0, t; }"
        : "=r"(a) : "l"(p));
    return a;
}
__device__ __forceinline__ void cvtr(uint32_t& r) {
    asm("cvt.rna.tf32.f32 %0, %0;" : "+r"(r));
}
__device__ __forceinline__ void cp16(uint32_t dst, const float* src) {
    asm volatile("cp.async.cg.shared.global [%0], [%1], 16;"
                 :: "r"(dst), "l"(src) : "memory");
}
__device__ __forceinline__ void cp_commit() {
    asm volatile("cp.async.commit_group;" ::: "memory");
}
__device__ __forceinline__ void cp_wait1() {
    asm volatile("cp.async.wait_group 1;" ::: "memory");
}
__device__ __forceinline__ void ldsm4(uint32_t& r0, uint32_t& r1,
                                      uint32_t& r2, uint32_t& r3, uint32_t addr) {
    asm volatile("ldmatrix.sync.aligned.m8n8.x4.shared.b16 {%0,%1,%2,%3}, [%4];"
                 : "=r"(r0), "=r"(r1), "=r"(r2), "=r"(r3) : "r"(addr));
}
__device__ __forceinline__ void mma8(float* c, const uint32_t* a,
                                     uint32_t b0, uint32_t b1) {
    asm volatile(
        "mma.sync.aligned.m16n8k8.row.col.f32.tf32.tf32.f32 "
        "{%0,%1,%2,%3}, {%4,%5,%6,%7}, {%8,%9}, {%0,%1,%2,%3};\n"
        : "+f"(c[0]), "+f"(c[1]), "+f"(c[2]), "+f"(c[3])
        : "r"(a[0]), "r"(a[1]), "r"(a[2]), "r"(a[3]), "r"(b0), "r"(b1));
}

__global__ void __launch_bounds__(256, 1) qkv_rope_tf32_cp3(
    const float* __restrict__ X, const float* __restrict__ Wq,
    const float* __restrict__ Wk, const float* __restrict__ Wv,
    const float* __restrict__ Ct, const float* __restrict__ St,
    float* __restrict__ Out)
{
    extern __shared__ __align__(1024) uint8_t smem[];
    const uint32_t sbase = cvta_smem(smem);

    const int tid  = threadIdx.x;
    const int lane = tid & 31;
    const int warp = tid >> 5;
    const int g  = lane >> 2;
    const int tg = lane & 3;
    const int wm = warp & 3;    // warp row (64 m each)
    const int wn = warp >> 2;   // warp col (64 n each)

    const int m0 = blockIdx.y * 256;
    const int n0 = blockIdx.x * 128;

    const float* Bpanel;
    if (n0 < 4096)      Bpanel = Wq + (size_t)n0 * 4096;
    else if (n0 < 5120) Bpanel = Wk + (size_t)(n0 - 4096) * 4096;
    else                Bpanel = Wv + (size_t)(n0 - 5120) * 4096;

    // ---- producers: cp.async, 8 A-chunks + 4 B-chunks (16B) per thread/k-tile
    const int prow = tid >> 3;          // 0..31
    const int pcol = tid & 7;           // 16B chunk within 128B row
    const float* aptr = X + (size_t)(m0 + prow) * 4096 + pcol * 4;
    const float* bptr = Bpanel + (size_t)prow * 4096 + pcol * 4;
    const uint32_t sA = sbase + prow * ROWB + pcol * 16;
    const uint32_t sB = sA + A_TILE;

    auto issue_cp = [&](int kt, int s) {
        const uint32_t so = (uint32_t)s * STAGE;
        const int ko = kt * 32;
        #pragma unroll
        for (int i = 0; i < 8; ++i)
            cp16(sA + so + i * (32 * ROWB), aptr + (size_t)i * 32 * 4096 + ko);
        #pragma unroll
        for (int i = 0; i < 4; ++i)
            cp16(sB + so + i * (32 * ROWB), bptr + (size_t)i * 32 * 4096 + ko);
        cp_commit();
    };

    // ---- ldmatrix offsets within a stage ----
    const int am = lane >> 3;           // matrix index 0..3
    const int ar = lane & 7;            // row within 8x8 matrix
    uint32_t aoff[4], boff[4];
    #pragma unroll
    for (int mt = 0; mt < 4; ++mt)
        aoff[mt] = (uint32_t)((wm * 64 + mt * 16 + (am & 1) * 8 + ar) * ROWB
                              + (am >> 1) * 16);
    #pragma unroll
    for (int p = 0; p < 4; ++p)
        boff[p] = (uint32_t)(A_TILE + (wn * 64 + p * 16 + (am >> 1) * 8 + ar) * ROWB
                             + (am & 1) * 16);

    float acc[4][8][4];
    #pragma unroll
    for (int i = 0; i < 4; ++i)
        #pragma unroll
        for (int j = 0; j < 8; ++j)
            #pragma unroll
            for (int c = 0; c < 4; ++c) acc[i][j][c] = 0.f;

    // prologue: 2 k-tiles in flight
    issue_cp(0, 0);
    issue_cp(1, 1);

    int stage = 0;       // stage of tile kt
    int nstage = 2;      // stage the next issued tile goes to
    for (int kt = 0; kt < NK; ++kt) {
        cp_wait1();                       // tile kt landed
        __syncthreads();
        if (kt + 2 < NK) {
            issue_cp(kt + 2, nstage);
            nstage = (nstage == STAGES - 1) ? 0 : nstage + 1;
        }

        const uint32_t sb = sbase + (uint32_t)stage * STAGE;
        stage = (stage == STAGES - 1) ? 0 : stage + 1;

        #pragma unroll
        for (int k8 = 0; k8 < 4; ++k8) {
            uint32_t af[4][4], bf[4][4];
            #pragma unroll
            for (int mt = 0; mt < 4; ++mt)
                ldsm4(af[mt][0], af[mt][1], af[mt][2], af[mt][3],
                      sb + aoff[mt] + k8 * 32);
            #pragma unroll
            for (int p = 0; p < 4; ++p)
                ldsm4(bf[p][0], bf[p][1], bf[p][2], bf[p][3],
                      sb + boff[p] + k8 * 32);
            #pragma unroll
            for (int mt = 0; mt < 4; ++mt)
                #pragma unroll
                for (int q = 0; q < 4; ++q) cvtr(af[mt][q]);
            #pragma unroll
            for (int p = 0; p < 4; ++p)
                #pragma unroll
                for (int q = 0; q < 4; ++q) cvtr(bf[p][q]);
            #pragma unroll
            for (int p = 0; p < 4; ++p)
                #pragma unroll
                for (int mt = 0; mt < 4; ++mt) {
                    mma8(acc[mt][2 * p],     af[mt], bf[p][0], bf[p][1]);
                    mma8(acc[mt][2 * p + 1], af[mt], bf[p][2], bf[p][3]);
                }
        }
        __syncthreads();                  // stage reads done before reuse
    }

    // ---- Epilogue: RoPE (q,k) + transpose to (B,H,S,D), concatenated [q|k|v] ----
    const bool isv = (n0 >= 5120);
    size_t base; int H, h;
    if (n0 < 4096)      { base = 0ull;                      H = 32; h = n0 >> 7; }
    else if (n0 < 5120) { base = 67108864ull;               H = 8;  h = (n0 - 4096) >> 7; }
    else                { base = 67108864ull + 16777216ull; H = 8;  h = (n0 - 5120) >> 7; }

    #pragma unroll
    for (int mt = 0; mt < 4; ++mt) {
        #pragma unroll
        for (int rh = 0; rh < 2; ++rh) {
            const int m = m0 + wm * 64 + mt * 16 + g + rh * 8;
            const int b = m >> 12;       // batch
            const int s = m & 4095;      // sequence position
            float* orow = Out + base + (((size_t)(b * H + h) * 4096 + (size_t)s) << 7);
            const float* cr = Ct + (size_t)s * 64;
            const float* sr = St + (size_t)s * 64;
            #pragma unroll
            for (int nt = 0; nt < 8; ++nt) {
                const int d = wn * 64 + nt * 8 + 2 * tg;   // even head-dim index
                float v0 = acc[mt][nt][rh * 2 + 0];
                float v1 = acc[mt][nt][rh * 2 + 1];
                if (!isv) {
                    const float cv = cr[d >> 1];
                    const float sv = sr[d >> 1];
                    const float t0 = v0 * cv - v1 * sv;
                    const float t1 = v0 * sv + v1 * cv;
                    v0 = t0; v1 = t1;
                }
                *reinterpret_cast<float2*>(orow + d) = make_float2(v0, v1);
            }
        }
    }
}

extern "C" void kernel_launch(void* const* d_in, const int* in_sizes, int n_in,
                              void* d_out, int out_size) {
    (void)in_sizes; (void)n_in; (void)out_size;
    const float* x  = (const float*)d_in[0];
    const float* wq = (const float*)d_in[1];
    const float* wk = (const float*)d_in[2];
    const float* wv = (const float*)d_in[3];
    const float* ct = (const float*)d_in[4];
    const float* st = (const float*)d_in[5];
    float* out = (float*)d_out;

    cudaFuncSetAttribute(qkv_rope_tf32_cp3,
                         cudaFuncAttributeMaxDynamicSharedMemorySize, SMEM_BYTES);
    dim3 grid(48, 64);   // 48 n-tiles (6144/128), 64 m-tiles (16384/256)
    qkv_rope_tf32_cp3<<<grid, 256, SMEM_BYTES>>>(x, wq, wk, wv, ct, st, out);
}

// round 14
// speedup vs baseline: 1.0369x; 1.0369x over previous
#include <cuda_runtime.h>
#include <cstdint>

// Fused QKV projection + RoPE + (B,H,S,D) transpose.
// tf32 mma.sync, 32x64 warp tiles, 2 CTAs/SM, cp.async 3-stage pipeline,
// consumer-side cvt.rna. BM=128 BN=128 BK=32, 256 threads.

namespace {
constexpr int NK = 128;                   // 4096/32 k-tiles
constexpr int ROWB = 144;                 // smem row pitch (128B data + 16B pad)
constexpr int A_TILE = 128 * ROWB;        // 18432
constexpr int STAGE = 2 * A_TILE;         // A + B = 36864
constexpr int STAGES = 3;
constexpr int SMEM_BYTES = STAGES * STAGE; // 110592 per CTA (2 CTAs = 221184)
}

__device__ __forceinline__ uint32_t cvta_smem(const void* p) {
    uint32_t a;
    asm("{ .reg .u64 t; cvta.to.shared.u64 t, %1; cvt.u32.u64 %0, t; }"
        : "=r"(a) : "l"(p));
    return a;
}
__device__ __forceinline__ void cvtr(uint32_t& r) {
    asm("cvt.rna.tf32.f32 %0, %0;" : "+r"(r));
}
__device__ __forceinline__ void cp16(uint32_t dst, const float* src) {
    asm volatile("cp.async.cg.shared.global [%0], [%1], 16;"
                 :: "r"(dst), "l"(src) : "memory");
}
__device__ __forceinline__ void cp_commit() {
    asm volatile("cp.async.commit_group;" ::: "memory");
}
__device__ __forceinline__ void cp_wait1() {
    asm volatile("cp.async.wait_group 1;" ::: "memory");
}
__device__ __forceinline__ void cp_wait0() {
    asm volatile("cp.async.wait_group 0;" ::: "memory");
}
__device__ __forceinline__ void ldsm4(uint32_t& r0, uint32_t& r1,
                                      uint32_t& r2, uint32_t& r3, uint32_t addr) {
    asm volatile("ldmatrix.sync.aligned.m8n8.x4.shared.b16 {%0,%1,%2,%3}, [%4];"
                 : "=r"(r0), "=r"(r1), "=r"(r2), "=r"(r3) : "r"(addr));
}
__device__ __forceinline__ void mma8(float* c, const uint32_t* a,
                                     uint32_t b0, uint32_t b1) {
    asm volatile(
        "mma.sync.aligned.m16n8k8.row.col.f32.tf32.tf32.f32 "
        "{%0,%1,%2,%3}, {%4,%5,%6,%7}, {%8,%9}, {%0,%1,%2,%3};\n"
        : "+f"(c[0]), "+f"(c[1]), "+f"(c[2]), "+f"(c[3])
        : "r"(a[0]), "r"(a[1]), "r"(a[2]), "r"(a[3]), "r"(b0), "r"(b1));
}

__global__ void __launch_bounds__(256, 2) qkv_rope_tf32_cp2cta(
    const float* __restrict__ X, const float* __restrict__ Wq,
    const float* __restrict__ Wk, const float* __restrict__ Wv,
    const float* __restrict__ Ct, const float* __restrict__ St,
    float* __restrict__ Out)
{
    extern __shared__ __align__(1024) uint8_t smem[];
    const uint32_t sbase = cvta_smem(smem);

    const int tid  = threadIdx.x;
    const int lane = tid & 31;
    const int warp = tid >> 5;
    const int g  = lane >> 2;
    const int tg = lane & 3;
    const int wm = warp & 3;    // warp row (32 m each)
    const int wn = warp >> 2;   // warp col (64 n each)

    const int m0 = blockIdx.y * 128;
    const int n0 = blockIdx.x * 128;

    const float* Bpanel;
    if (n0 < 4096)      Bpanel = Wq + (size_t)n0 * 4096;
    else if (n0 < 5120) Bpanel = Wk + (size_t)(n0 - 4096) * 4096;
    else                Bpanel = Wv + (size_t)(n0 - 5120) * 4096;

    // ---- producers: cp.async, 4 A-chunks + 4 B-chunks (16B) per thread/k-tile
    const int prow = tid >> 3;          // 0..31
    const int pcol = tid & 7;           // 16B chunk within 128B row
    const float* aptr = X + (size_t)(m0 + prow) * 4096 + pcol * 4;
    const float* bptr = Bpanel + (size_t)prow * 4096 + pcol * 4;
    const uint32_t sA = sbase + prow * ROWB + pcol * 16;
    const uint32_t sB = sA + A_TILE;

    auto issue_cp = [&](int kt, int s) {
        const uint32_t so = (uint32_t)s * STAGE;
        const int ko = kt * 32;
        #pragma unroll
        for (int i = 0; i < 4; ++i)
            cp16(sA + so + i * (32 * ROWB), aptr + (size_t)i * 32 * 4096 + ko);
        #pragma unroll
        for (int i = 0; i < 4; ++i)
            cp16(sB + so + i * (32 * ROWB), bptr + (size_t)i * 32 * 4096 + ko);
        cp_commit();
    };

    // ---- ldmatrix offsets within a stage ----
    const int am = lane >> 3;           // matrix index 0..3
    const int ar = lane & 7;            // row within 8x8 matrix
    uint32_t aoff[2], boff[4];
    #pragma unroll
    for (int mt = 0; mt < 2; ++mt)
        aoff[mt] = (uint32_t)((wm * 32 + mt * 16 + (am & 1) * 8 + ar) * ROWB
                              + (am >> 1) * 16);
    #pragma unroll
    for (int p = 0; p < 4; ++p)
        boff[p] = (uint32_t)(A_TILE + (wn * 64 + p * 16 + (am >> 1) * 8 + ar) * ROWB
                             + (am & 1) * 16);

    float acc[2][8][4];
    #pragma unroll
    for (int i = 0; i < 2; ++i)
        #pragma unroll
        for (int j = 0; j < 8; ++j)
            #pragma unroll
            for (int c = 0; c < 4; ++c) acc[i][j][c] = 0.f;

    // prologue: 2 k-tiles in flight
    issue_cp(0, 0);
    issue_cp(1, 1);

    int stage = 0;       // stage holding tile kt
    int nstage = 2;      // stage for the next issued tile
    for (int kt = 0; kt < NK; ++kt) {
        if (kt + 1 < NK) cp_wait1(); else cp_wait0();   // tile kt landed
        __syncthreads();   // publish tile kt to all warps; fences stage reuse
        if (kt + 2 < NK) {
            issue_cp(kt + 2, nstage);
            nstage = (nstage == STAGES - 1) ? 0 : nstage + 1;
        }

        const uint32_t sb = sbase + (uint32_t)stage * STAGE;
        stage = (stage == STAGES - 1) ? 0 : stage + 1;

        #pragma unroll
        for (int k8 = 0; k8 < 4; ++k8) {
            uint32_t af[2][4], bf[4][4];
            ldsm4(af[0][0], af[0][1], af[0][2], af[0][3], sb + aoff[0] + k8 * 32);
            ldsm4(af[1][0], af[1][1], af[1][2], af[1][3], sb + aoff[1] + k8 * 32);
            #pragma unroll
            for (int p = 0; p < 4; ++p)
                ldsm4(bf[p][0], bf[p][1], bf[p][2], bf[p][3],
                      sb + boff[p] + k8 * 32);
            #pragma unroll
            for (int mt = 0; mt < 2; ++mt)
                #pragma unroll
                for (int q = 0; q < 4; ++q) cvtr(af[mt][q]);
            #pragma unroll
            for (int p = 0; p < 4; ++p)
                #pragma unroll
                for (int q = 0; q < 4; ++q) cvtr(bf[p][q]);
            #pragma unroll
            for (int p = 0; p < 4; ++p)
                #pragma unroll
                for (int mt = 0; mt < 2; ++mt) {
                    mma8(acc[mt][2 * p],     af[mt], bf[p][0], bf[p][1]);
                    mma8(acc[mt][2 * p + 1], af[mt], bf[p][2], bf[p][3]);
                }
        }
    }

    // ---- Epilogue: RoPE (q,k) + transpose to (B,H,S,D), concatenated [q|k|v] ----
    const bool isv = (n0 >= 5120);
    size_t base; int H, h;
    if (n0 < 4096)      { base = 0ull;                      H = 32; h = n0 >> 7; }
    else if (n0 < 5120) { base = 67108864ull;               H = 8;  h = (n0 - 4096) >> 7; }
    else                { base = 67108864ull + 16777216ull; H = 8;  h = (n0 - 5120) >> 7; }

    #pragma unroll
    for (int mt = 0; mt < 2; ++mt) {
        #pragma unroll
        for (int rh = 0; rh < 2; ++rh) {
            const int m = m0 + wm * 32 + mt * 16 + g + rh * 8;
            const int b = m >> 12;       // batch
            const int s = m & 4095;      // sequence position
            float* orow = Out + base + (((size_t)(b * H + h) * 4096 + (size_t)s) << 7);
            const float* cr = Ct + (size_t)s * 64;
            const float* sr = St + (size_t)s * 64;
            #pragma unroll
            for (int nt = 0; nt < 8; ++nt) {
                const int d = wn * 64 + nt * 8 + 2 * tg;   // even head-dim index
                float v0 = acc[mt][nt][rh * 2 + 0];
                float v1 = acc[mt][nt][rh * 2 + 1];
                if (!isv) {
                    const float cv = cr[d >> 1];
                    const float sv = sr[d >> 1];
                    const float t0 = v0 * cv - v1 * sv;
                    const float t1 = v0 * sv + v1 * cv;
                    v0 = t0; v1 = t1;
                }
                *reinterpret_cast<float2*>(orow + d) = make_float2(v0, v1);
            }
        }
    }
}

extern "C" void kernel_launch(void* const* d_in, const int* in_sizes, int n_in,
                              void* d_out, int out_size) {
    (void)in_sizes; (void)n_in; (void)out_size;
    const float* x  = (const float*)d_in[0];
    const float* wq = (const float*)d_in[1];
    const float* wk = (const float*)d_in[2];
    const float* wv = (const float*)d_in[3];
    const float* ct = (const float*)d_in[4];
    const float* st = (const float*)d_in[5];
    float* out = (float*)d_out;

    cudaFuncSetAttribute(qkv_rope_tf32_cp2cta,
                         cudaFuncAttributeMaxDynamicSharedMemorySize, SMEM_BYTES);
    dim3 grid(48, 128);   // 48 n-tiles (6144/128), 128 m-tiles (16384/128)
    qkv_rope_tf32_cp2cta<<<grid, 256, SMEM_BYTES>>>(x, wq, wk, wv, ct, st, out);
}

// round 15
// speedup vs baseline: 1.1999x; 1.1572x over previous
#include <cuda_runtime.h>
#include <cstdint>

// Fused QKV projection + RoPE + (B,H,S,D) transpose.
// Round-to-tf32 prepass into __device__ scratch, then cvt-free tf32 mma.sync
// mainloop: 32x64 warp tiles, 2 CTAs/SM, cp.async 3-stage, fragment
// double-buffering across k8.  BM=128 BN=128 BK=32, 256 threads.

namespace {
constexpr int NK = 128;                   // 4096/32 k-tiles
constexpr int ROWB = 144;                 // smem row pitch (128B data + 16B pad)
constexpr int A_TILE = 128 * ROWB;        // 18432
constexpr int STAGE = 2 * A_TILE;         // A + B = 36864
constexpr int STAGES = 3;
constexpr int SMEM_BYTES = STAGES * STAGE; // 110592 per CTA (2 CTAs = 221184)
}

// Pre-rounded (tf32) copies. X: 16384x4096. W: [q|k|v] rows = 6144x4096.
__device__ float g_Xr[(size_t)16384 * 4096];
__device__ float g_Wr[(size_t)6144 * 4096];

__device__ __forceinline__ uint32_t cvta_smem(const void* p) {
    uint32_t a;
    asm("{ .reg .u64 t; cvta.to.shared.u64 t, %1; cvt.u32.u64 %0, t; }"
        : "=r"(a) : "l"(p));
    return a;
}
__device__ __forceinline__ float f2tf_f(float f) {
    uint32_t r; asm("cvt.rna.tf32.f32 %0, %1;" : "=r"(r) : "f"(f));
    return __uint_as_float(r);
}
__device__ __forceinline__ void cp16(uint32_t dst, const float* src) {
    asm volatile("cp.async.cg.shared.global [%0], [%1], 16;"
                 :: "r"(dst), "l"(src) : "memory");
}
__device__ __forceinline__ void cp_commit() {
    asm volatile("cp.async.commit_group;" ::: "memory");
}
__device__ __forceinline__ void cp_wait1() {
    asm volatile("cp.async.wait_group 1;" ::: "memory");
}
__device__ __forceinline__ void cp_wait0() {
    asm volatile("cp.async.wait_group 0;" ::: "memory");
}
__device__ __forceinline__ void ldsm4(uint32_t& r0, uint32_t& r1,
                                      uint32_t& r2, uint32_t& r3, uint32_t addr) {
    asm volatile("ldmatrix.sync.aligned.m8n8.x4.shared.b16 {%0,%1,%2,%3}, [%4];"
                 : "=r"(r0), "=r"(r1), "=r"(r2), "=r"(r3) : "r"(addr));
}
__device__ __forceinline__ void mma8(float* c, const uint32_t* a,
                                     uint32_t b0, uint32_t b1) {
    asm volatile(
        "mma.sync.aligned.m16n8k8.row.col.f32.tf32.tf32.f32 "
        "{%0,%1,%2,%3}, {%4,%5,%6,%7}, {%8,%9}, {%0,%1,%2,%3};\n"
        : "+f"(c[0]), "+f"(c[1]), "+f"(c[2]), "+f"(c[3])
        : "r"(a[0]), "r"(a[1]), "r"(a[2]), "r"(a[3]), "r"(b0), "r"(b1));
}

// ---- prepass: round once per element into __device__ scratch ----
__global__ void __launch_bounds__(256) round_tf32_pass(
    const float* __restrict__ X,  const float* __restrict__ Wq,
    const float* __restrict__ Wk, const float* __restrict__ Wv)
{
    const size_t stride = (size_t)gridDim.x * blockDim.x;
    const size_t i0 = (size_t)blockIdx.x * blockDim.x + threadIdx.x;

    const size_t NX4 = (size_t)16384 * 4096 / 4;   // 16777216
    const size_t NQ4 = (size_t)4096 * 4096 / 4;    // 4194304
    const size_t NKV4 = (size_t)1024 * 4096 / 4;   // 1048576

    float4* xr = reinterpret_cast<float4*>(g_Xr);
    float4* wr = reinterpret_cast<float4*>(g_Wr);
    const float4* xs = reinterpret_cast<const float4*>(X);
    const float4* qs = reinterpret_cast<const float4*>(Wq);
    const float4* ks = reinterpret_cast<const float4*>(Wk);
    const float4* vs = reinterpret_cast<const float4*>(Wv);

    for (size_t j = i0; j < NX4; j += stride) {
        float4 v = xs[j];
        xr[j] = make_float4(f2tf_f(v.x), f2tf_f(v.y), f2tf_f(v.z), f2tf_f(v.w));
    }
    for (size_t j = i0; j < NQ4; j += stride) {
        float4 v = qs[j];
        wr[j] = make_float4(f2tf_f(v.x), f2tf_f(v.y), f2tf_f(v.z), f2tf_f(v.w));
    }
    for (size_t j = i0; j < NKV4; j += stride) {
        float4 v = ks[j];
        wr[NQ4 + j] = make_float4(f2tf_f(v.x), f2tf_f(v.y), f2tf_f(v.z), f2tf_f(v.w));
        float4 u = vs[j];
        wr[NQ4 + NKV4 + j] = make_float4(f2tf_f(u.x), f2tf_f(u.y), f2tf_f(u.z), f2tf_f(u.w));
    }
}

__global__ void __launch_bounds__(256, 2) qkv_rope_tf32_nocvt(
    const float* __restrict__ Ct, const float* __restrict__ St,
    float* __restrict__ Out)
{
    extern __shared__ __align__(1024) uint8_t smem[];
    const uint32_t sbase = cvta_smem(smem);

    const int tid  = threadIdx.x;
    const int lane = tid & 31;
    const int warp = tid >> 5;
    const int g  = lane >> 2;
    const int tg = lane & 3;
    const int wm = warp & 3;    // warp row (32 m each)
    const int wn = warp >> 2;   // warp col (64 n each)

    const int m0 = blockIdx.y * 128;
    const int n0 = blockIdx.x * 128;

    // ---- producers: cp.async, 4 A-chunks + 4 B-chunks (16B) per thread/k-tile
    const int prow = tid >> 3;          // 0..31
    const int pcol = tid & 7;           // 16B chunk within 128B row
    const float* aptr = g_Xr + (size_t)(m0 + prow) * 4096 + pcol * 4;
    const float* bptr = g_Wr + (size_t)(n0 + prow) * 4096 + pcol * 4;
    const uint32_t sA = sbase + prow * ROWB + pcol * 16;
    const uint32_t sB = sA + A_TILE;

    auto issue_cp = [&](int kt, int s) {
        const uint32_t so = (uint32_t)s * STAGE;
        const int ko = kt * 32;
        #pragma unroll
        for (int i = 0; i < 4; ++i)
            cp16(sA + so + i * (32 * ROWB), aptr + (size_t)i * 32 * 4096 + ko);
        #pragma unroll
        for (int i = 0; i < 4; ++i)
            cp16(sB + so + i * (32 * ROWB), bptr + (size_t)i * 32 * 4096 + ko);
        cp_commit();
    };

    // ---- ldmatrix offsets within a stage ----
    const int am = lane >> 3;           // matrix index 0..3
    const int ar = lane & 7;            // row within 8x8 matrix
    uint32_t aoff[2], boff[4];
    #pragma unroll
    for (int mt = 0; mt < 2; ++mt)
        aoff[mt] = (uint32_t)((wm * 32 + mt * 16 + (am & 1) * 8 + ar) * ROWB
                              + (am >> 1) * 16);
    #pragma unroll
    for (int p = 0; p < 4; ++p)
        boff[p] = (uint32_t)(A_TILE + (wn * 64 + p * 16 + (am >> 1) * 8 + ar) * ROWB
                             + (am & 1) * 16);

    float acc[2][8][4];
    #pragma unroll
    for (int i = 0; i < 2; ++i)
        #pragma unroll
        for (int j = 0; j < 8; ++j)
            #pragma unroll
            for (int c = 0; c < 4; ++c) acc[i][j][c] = 0.f;

    // prologue: 2 k-tiles in flight
    issue_cp(0, 0);
    issue_cp(1, 1);

    uint32_t af[2][2][4], bf[2][4][4];   // double-buffered fragments

    int stage = 0;       // stage holding tile kt
    int nstage = 2;      // stage for the next issued tile
    for (int kt = 0; kt < NK; ++kt) {
        if (kt + 1 < NK) cp_wait1(); else cp_wait0();   // tile kt landed
        __syncthreads();   // publish tile kt; fences stage reuse (depth-2 ring)
        if (kt + 2 < NK) {
            issue_cp(kt + 2, nstage);
            nstage = (nstage == STAGES - 1) ? 0 : nstage + 1;
        }

        const uint32_t sb = sbase + (uint32_t)stage * STAGE;
        stage = (stage == STAGES - 1) ? 0 : stage + 1;

        // preload k8=0 fragments into buffer 0
        ldsm4(af[0][0][0], af[0][0][1], af[0][0][2], af[0][0][3], sb + aoff[0]);
        ldsm4(af[0][1][0], af[0][1][1], af[0][1][2], af[0][1][3], sb + aoff[1]);
        #pragma unroll
        for (int p = 0; p < 4; ++p)
            ldsm4(bf[0][p][0], bf[0][p][1], bf[0][p][2], bf[0][p][3], sb + boff[p]);

        #pragma unroll
        for (int k8 = 0; k8 < 4; ++k8) {
            const int cur = k8 & 1;
            const int nxt = cur ^ 1;
            if (k8 < 3) {   // overlap next k8's ldsm with this k8's mma
                const uint32_t ko = (k8 + 1) * 32;
                ldsm4(af[nxt][0][0], af[nxt][0][1], af[nxt][0][2], af[nxt][0][3],
                      sb + aoff[0] + ko);
                ldsm4(af[nxt][1][0], af[nxt][1][1], af[nxt][1][2], af[nxt][1][3],
                      sb + aoff[1] + ko);
                #pragma unroll
                for (int p = 0; p < 4; ++p)
                    ldsm4(bf[nxt][p][0], bf[nxt][p][1], bf[nxt][p][2], bf[nxt][p][3],
                          sb + boff[p] + ko);
            }
            #pragma unroll
            for (int p = 0; p < 4; ++p)
                #pragma unroll
                for (int mt = 0; mt < 2; ++mt) {
                    mma8(acc[mt][2 * p],     af[cur][mt], bf[cur][p][0], bf[cur][p][1]);
                    mma8(acc[mt][2 * p + 1], af[cur][mt], bf[cur][p][2], bf[cur][p][3]);
                }
        }
    }

    // ---- Epilogue: RoPE (q,k) + transpose to (B,H,S,D), concatenated [q|k|v] ----
    const bool isv = (n0 >= 5120);
    size_t base; int H, h;
    if (n0 < 4096)      { base = 0ull;                      H = 32; h = n0 >> 7; }
    else if (n0 < 5120) { base = 67108864ull;               H = 8;  h = (n0 - 4096) >> 7; }
    else                { base = 67108864ull + 16777216ull; H = 8;  h = (n0 - 5120) >> 7; }

    #pragma unroll
    for (int mt = 0; mt < 2; ++mt) {
        #pragma unroll
        for (int rh = 0; rh < 2; ++rh) {
            const int m = m0 + wm * 32 + mt * 16 + g + rh * 8;
            const int b = m >> 12;       // batch
            const int s = m & 4095;      // sequence position
            float* orow = Out + base + (((size_t)(b * H + h) * 4096 + (size_t)s) << 7);
            const float* cr = Ct + (size_t)s * 64;
            const float* sr = St + (size_t)s * 64;
            #pragma unroll
            for (int nt = 0; nt < 8; ++nt) {
                const int d = wn * 64 + nt * 8 + 2 * tg;   // even head-dim index
                float v0 = acc[mt][nt][rh * 2 + 0];
                float v1 = acc[mt][nt][rh * 2 + 1];
                if (!isv) {
                    const float cv = cr[d >> 1];
                    const float sv = sr[d >> 1];
                    const float t0 = v0 * cv - v1 * sv;
                    const float t1 = v0 * sv + v1 * cv;
                    v0 = t0; v1 = t1;
                }
                *reinterpret_cast<float2*>(orow + d) = make_float2(v0, v1);
            }
        }
    }
}

extern "C" void kernel_launch(void* const* d_in, const int* in_sizes, int n_in,
                              void* d_out, int out_size) {
    (void)in_sizes; (void)n_in; (void)out_size;
    const float* x  = (const float*)d_in[0];
    const float* wq = (const float*)d_in[1];
    const float* wk = (const float*)d_in[2];
    const float* wv = (const float*)d_in[3];
    const float* ct = (const float*)d_in[4];
    const float* st = (const float*)d_in[5];
    float* out = (float*)d_out;

    round_tf32_pass<<<2048, 256>>>(x, wq, wk, wv);

    cudaFuncSetAttribute(qkv_rope_tf32_nocvt,
                         cudaFuncAttributeMaxDynamicSharedMemorySize, SMEM_BYTES);
    dim3 grid(48, 128);   // 48 n-tiles (6144/128), 128 m-tiles (16384/128)
    qkv_rope_tf32_nocvt<<<grid, 256, SMEM_BYTES>>>(ct, st, out);
}